// round 13
// baseline (speedup 1.0000x reference)
#include <cuda_runtime.h>
#include <cuda_fp16.h>

#define BB 32
#define DD 512
#define KK 64
#define NNN 1024

typedef unsigned int u32;

// Scratch (__device__ globals; allocation-free rule)
__device__ __align__(16) __half g_xh[(size_t)BB * DD * NNN];     // 33.5 MB fp16 x
__device__ __align__(16) __half g_assign[(size_t)BB * KK * NNN]; // 4 MB fp16 assign
__device__ __align__(16) float g_asum_part[(size_t)BB * 8 * KK];
__device__ __align__(16) float g_vlad[(size_t)BB * DD * KK];     // 4 MB

// ---------------- helpers ----------------
__device__ __forceinline__ u32 smem_u32(const void* p) {
    u32 a;
    asm("{ .reg .u64 t; cvta.to.shared.u64 t, %1; cvt.u32.u64 %0, t; }" : "=r"(a) : "l"(p));
    return a;
}
__device__ __forceinline__ u32 pack_h2(float a, float b) {
    u32 r;
    asm("cvt.rn.f16x2.f32 %0, %1, %2;" : "=r"(r) : "f"(b), "f"(a));
    return r;
}
__device__ __forceinline__ void mma16816h(float* c, const u32* a, u32 b0, u32 b1) {
    asm volatile(
        "mma.sync.aligned.m16n8k16.row.col.f32.f16.f16.f32 "
        "{%0,%1,%2,%3},{%4,%5,%6,%7},{%8,%9},{%0,%1,%2,%3};"
        : "+f"(c[0]), "+f"(c[1]), "+f"(c[2]), "+f"(c[3])
        : "r"(a[0]), "r"(a[1]), "r"(a[2]), "r"(a[3]), "r"(b0), "r"(b1));
}
__device__ __forceinline__ void ldsm4(u32* r, u32 a) {
    asm volatile("ldmatrix.sync.aligned.m8n8.x4.shared.b16 {%0,%1,%2,%3}, [%4];"
                 : "=r"(r[0]), "=r"(r[1]), "=r"(r[2]), "=r"(r[3]) : "r"(a));
}
__device__ __forceinline__ void ldsm4t(u32* r, u32 a) {
    asm volatile("ldmatrix.sync.aligned.m8n8.x4.trans.shared.b16 {%0,%1,%2,%3}, [%4];"
                 : "=r"(r[0]), "=r"(r[1]), "=r"(r[2]), "=r"(r[3]) : "r"(a));
}
__device__ __forceinline__ void sts128u(u32 a, uint4 v) {
    asm volatile("st.shared.v4.b32 [%0], {%1,%2,%3,%4};"
                 :: "r"(a), "r"(v.x), "r"(v.y), "r"(v.z), "r"(v.w));
}
__device__ __forceinline__ uint4 lds128u(u32 a) {
    uint4 v;
    asm volatile("ld.shared.v4.b32 {%0,%1,%2,%3}, [%4];"
                 : "=r"(v.x), "=r"(v.y), "=r"(v.z), "=r"(v.w) : "r"(a));
    return v;
}
__device__ __forceinline__ void cpasync16(u32 dst, const void* src) {
    asm volatile("cp.async.cg.shared.global [%0], [%1], 16;" :: "r"(dst), "l"(src));
}
__device__ __forceinline__ void cp_commit() {
    asm volatile("cp.async.commit_group;" ::: "memory");
}
template <int N>
__device__ __forceinline__ void cp_wait() {
    asm volatile("cp.async.wait_group %0;" :: "n"(N) : "memory");
}
// 8 floats -> 1 uint4 of fp16
__device__ __forceinline__ void cvt8h(const float* f, uint4& h) {
    u32* hp = (u32*)&h;
#pragma unroll
    for (int j = 0; j < 4; j++) hp[j] = pack_h2(f[2 * j], f[2 * j + 1]);
}

// ---------------------------------------------------------------------------
// K1 v2: D[n=256, k=64] = x^T W^T, fp16 single planes. cp.async 3-stage ring
// for fp32 x; convert phase produces fp16 MMA buffer + g_xh; W fp16 resident.
// Fused softmax, assign fp16 (k-major) + asum partials.
// Grid (4, 32), 512 thr (16 warps, warp tile 64n x 16k), 1 CTA/SM.
// Smem: Xring 3 x [32 d][1040B] = 99840 | W [64 k][1040B] = 66560 @ 99840
//       Xh 2 x [32 d][528B] = 33792 @ 166400. Total 200192.
// Score overlay f32[256][65] = 66560 reuses the ring region.
// ---------------------------------------------------------------------------
__global__ void __launch_bounds__(512, 1)
k1_scores(const float* __restrict__ x, const float* __restrict__ w) {
    extern __shared__ __align__(16) char dyn[];
    float* smf = reinterpret_cast<float*>(dyn);
    const u32 sb = smem_u32(dyn);
    const u32 WR = sb + 99840u;
    const u32 XH = sb + 166400u;

    const int tid = threadIdx.x;
    const int b   = blockIdx.y;
    const int n0  = blockIdx.x * 256;
    const float* xb = x + (size_t)b * DD * NNN;

    const int lane = tid & 31, wid = tid >> 5;
    const int wm = wid >> 2, wnk = wid & 3;   // n block 64*wm, k block 16*wnk
    const int g = lane >> 2, tig = lane & 3;
    const int fr = lane & 7, fi = lane >> 3;

    const u32 aoff0 = (u32)(((fi >> 1) * 8 + fr) * 528 + (wm * 64 + (fi & 1) * 8) * 2);
    const u32 boff0 = (u32)((wnk * 16 + (fi >> 1) * 8 + fr) * 1040 + (fi & 1) * 16);

    float c[4][2][4];
#pragma unroll
    for (int i = 0; i < 4; i++)
#pragma unroll
        for (int j = 0; j < 2; j++)
#pragma unroll
            for (int q = 0; q < 4; q++) c[i][j][q] = 0.f;

    // cp.async issue for chunk ch (32 d x 256 n fp32 = 2048 x 16B)
    auto issue = [&](int ch) {
        const u32 ST = sb + (u32)(ch % 3) * 33280u;
        const int nc = ch * 32;
#pragma unroll
        for (int r = 0; r < 4; r++) {
            const int idx = tid + r * 512;
            const int row = idx >> 6, piece = idx & 63;
            cpasync16(ST + (u32)(row * 1040 + piece * 16),
                      xb + (size_t)(nc + row) * NNN + n0 + piece * 4);
        }
    };

    // prologue: start x pipeline, then stage W (fp32 LDG -> fp16 resident)
    issue(0); cp_commit();
    issue(1); cp_commit();
    issue(2); cp_commit();
    {
        const int wk = tid >> 3;          // k row 0..63
        const int seg = (tid & 7) * 64;   // 64 d per thread
#pragma unroll
        for (int i = 0; i < 8; i++) {
            const int d = seg + i * 8;
            float4 v0 = *(const float4*)(w + (size_t)wk * DD + d);
            float4 v1 = *(const float4*)(w + (size_t)wk * DD + d + 4);
            float f[8] = {v0.x, v0.y, v0.z, v0.w, v1.x, v1.y, v1.z, v1.w};
            uint4 h;
            cvt8h(f, h);
            sts128u(WR + (u32)(wk * 1040 + d * 2), h);
        }
    }

    const int NCH = 16;
    for (int ch = 0; ch < NCH; ch++) {
        cp_wait<2>();
        __syncthreads();                 // chunk ch fp32 visible; W ready (ch==0)
        // convert: fp32 ring -> fp16 MMA buf + g_xh
        {
            const u32 ST = sb + (u32)(ch % 3) * 33280u;
            const int row = tid >> 4, grp = tid & 15;
            const u32 src = ST + (u32)(row * 1040 + grp * 64);
            uint4 a0 = lds128u(src), a1 = lds128u(src + 16);
            uint4 a2 = lds128u(src + 32), a3 = lds128u(src + 48);
            float f[16];
            *(uint4*)(f)      = a0; *(uint4*)(f + 4)  = a1;
            *(uint4*)(f + 8)  = a2; *(uint4*)(f + 12) = a3;
            uint4 h0, h1;
            cvt8h(f, h0); cvt8h(f + 8, h1);
            const u32 dst = XH + (u32)((ch & 1) * 16896 + row * 528 + grp * 32);
            sts128u(dst, h0); sts128u(dst + 16, h1);
            __half* xo = g_xh + ((size_t)b * DD + ch * 32 + row) * NNN + n0 + grp * 16;
            *reinterpret_cast<uint4*>(xo) = h0;
            *reinterpret_cast<uint4*>(xo + 8) = h1;
        }
        __syncthreads();                 // fp16 buf complete; ring stage free
        if (ch + 3 < NCH) issue(ch + 3);
        cp_commit();
        // MMA from Xh[ch&1] + resident W
        const u32 XB = XH + (u32)((ch & 1) * 16896);
#pragma unroll
        for (int ks = 0; ks < 2; ks++) {
            u32 bh[4];
            ldsm4(bh, WR + boff0 + (u32)(ch * 64 + ks * 32));
            u32 ah[4][4];
#pragma unroll
            for (int mt = 0; mt < 4; mt++)
                ldsm4t(ah[mt], XB + aoff0 + (u32)(ks * 8448 + mt * 32));
#pragma unroll
            for (int mt = 0; mt < 4; mt++)
#pragma unroll
                for (int nt = 0; nt < 2; nt++)
                    mma16816h(c[mt][nt], ah[mt], bh[2 * nt], bh[2 * nt + 1]);
        }
    }
    __syncthreads();   // mainloop done; overlay ring region with scores

    // scores -> smem overlay [256][65] f32
#pragma unroll
    for (int mt = 0; mt < 4; mt++) {
        const int r0 = wm * 64 + mt * 16 + g;
#pragma unroll
        for (int nt = 0; nt < 2; nt++) {
            const int col = wnk * 16 + nt * 8 + 2 * tig;
            smf[r0 * 65 + col]           = c[mt][nt][0];
            smf[r0 * 65 + col + 1]       = c[mt][nt][1];
            smf[(r0 + 8) * 65 + col]     = c[mt][nt][2];
            smf[(r0 + 8) * 65 + col + 1] = c[mt][nt][3];
        }
    }
    __syncthreads();

    // softmax over k per n-row
    if (tid < 256) {
        float r[64];
#pragma unroll
        for (int i = 0; i < 64; i++) r[i] = smf[tid * 65 + i];
        float mx = r[0];
#pragma unroll
        for (int i = 1; i < 64; i++) mx = fmaxf(mx, r[i]);
        float s = 0.f;
#pragma unroll
        for (int i = 0; i < 64; i++) { r[i] = __expf(r[i] - mx); s += r[i]; }
        const float is = 1.f / s;
#pragma unroll
        for (int i = 0; i < 64; i++) smf[tid * 65 + i] = r[i] * is;
    }
    __syncthreads();

    if (tid < 64) {  // asum partial for this n-tile (4 tiles per b)
        float s = 0.f;
        for (int rw = 0; rw < 256; rw++) s += smf[rw * 65 + tid];
        g_asum_part[((size_t)b * 8 + blockIdx.x) * KK + tid] = s;
    }
    {   // assign -> fp16 single plane, k-major
        const int k  = tid >> 3;
        const int ns = (tid & 7) * 32;
        __half* oh = g_assign + ((size_t)b * KK + k) * NNN + n0 + ns;
#pragma unroll
        for (int j = 0; j < 32; j += 2) {
            float a0 = smf[(ns + j) * 65 + k];
            float a1 = smf[(ns + j + 1) * 65 + k];
            *reinterpret_cast<u32*>(oh + j) = pack_h2(a0, a1);
        }
    }
}

// ---------------------------------------------------------------------------
// K2: D[d=64, k=64] = x_h · assign^T over n=1024, 4-stage cp.async pipeline,
// n-chunk 64 (16 chunks). Grid (8, 32) = 256 CTAs, 256 thr, 2 CTA/SM.
// Warp tile 32d x 16k (8 warps). Fused "- centers * asum" epilogue.
// Dyn smem: A[4][64 x 144B] = 36864; B[4][64 x 144B] = 36864. Total 73728.
// ---------------------------------------------------------------------------
__global__ void __launch_bounds__(256, 2)
k2_vlad(const float* __restrict__ centers) {
    extern __shared__ __align__(16) char dyn[];
    __shared__ float s_asum[KK];
    const u32 sb = smem_u32(dyn);

    const int tid = threadIdx.x;
    const int b   = blockIdx.y;
    const int d0  = blockIdx.x * 64;

    const int lane = tid & 31, wid = tid >> 5;
    const int wm = wid >> 2, wn = wid & 3;
    const int g = lane >> 2, tig = lane & 3;
    const int fr = lane & 7, fi = lane >> 3;

    const u32 aoff0 = (u32)((wm * 32 + (fi & 1) * 8 + fr) * 144 + ((fi >> 1) * 8) * 2);
    const u32 boff0 = (u32)((wn * 16 + (fi >> 1) * 8 + fr) * 144 + (fi & 1) * 16);

    if (tid < 64) {
        float s = 0.f;
#pragma unroll
        for (int q = 0; q < 4; q++) s += g_asum_part[((size_t)b * 8 + q) * KK + tid];
        s_asum[tid] = s;
    }

    const __half* xhp = g_xh + ((size_t)b * DD + d0) * NNN;
    const __half* ahp = g_assign + (size_t)b * KK * NNN;

    float c[2][2][4];
#pragma unroll
    for (int i = 0; i < 2; i++)
#pragma unroll
        for (int j = 0; j < 2; j++)
#pragma unroll
            for (int q = 0; q < 4; q++) c[i][j][q] = 0.f;

    auto issue = [&](int ch) {
        const int st = ch & 3;
        const int nc = ch * 64;
        const u32 AB = sb + (u32)st * 9216u;
        const u32 BBF = sb + 36864u + (u32)st * 9216u;
#pragma unroll
        for (int r = 0; r < 2; r++) {
            const int cidx = tid + r * 256;
            const int row = cidx >> 3, piece = cidx & 7;
            cpasync16(AB + (u32)(row * 144 + piece * 16),
                      xhp + (size_t)row * NNN + nc + piece * 8);
            cpasync16(BBF + (u32)(row * 144 + piece * 16),
                      ahp + (size_t)row * NNN + nc + piece * 8);
        }
    };

    issue(0); cp_commit();
    issue(1); cp_commit();
    issue(2); cp_commit();

    const int NCH = 16;
    for (int ch = 0; ch < NCH; ch++) {
        cp_wait<2>();
        __syncthreads();
        const u32 AH = sb + (u32)(ch & 3) * 9216u;
        const u32 BH = sb + 36864u + (u32)(ch & 3) * 9216u;
#pragma unroll
        for (int ks = 0; ks < 4; ks++) {
            u32 bh[4];
            ldsm4(bh, BH + boff0 + ks * 32);
            u32 ah[2][4];
#pragma unroll
            for (int mt = 0; mt < 2; mt++)
                ldsm4(ah[mt], AH + aoff0 + ks * 32 + (u32)mt * 2304u);
#pragma unroll
            for (int mt = 0; mt < 2; mt++)
#pragma unroll
                for (int nt = 0; nt < 2; nt++)
                    mma16816h(c[mt][nt], ah[mt], bh[2 * nt], bh[2 * nt + 1]);
        }
        __syncthreads();
        if (ch + 3 < NCH) issue(ch + 3);
        cp_commit();
    }

    // epilogue: vlad[d][k] = D - centers[d][k] * asum[k]
#pragma unroll
    for (int mt = 0; mt < 2; mt++) {
        const int dr0 = d0 + wm * 32 + mt * 16 + g;
        const int dr1 = dr0 + 8;
#pragma unroll
        for (int nt = 0; nt < 2; nt++) {
            const int k = wn * 16 + nt * 8 + 2 * tig;
            const float as0 = s_asum[k], as1 = s_asum[k + 1];
            float2 cv0 = *(const float2*)(centers + (size_t)dr0 * KK + k);
            float2 o0  = make_float2(c[mt][nt][0] - cv0.x * as0,
                                     c[mt][nt][1] - cv0.y * as1);
            *(float2*)(g_vlad + ((size_t)b * DD + dr0) * KK + k) = o0;
            float2 cv1 = *(const float2*)(centers + (size_t)dr1 * KK + k);
            float2 o1  = make_float2(c[mt][nt][2] - cv1.x * as0,
                                     c[mt][nt][3] - cv1.y * as1);
            *(float2*)(g_vlad + ((size_t)b * DD + dr1) * KK + k) = o1;
        }
    }
}

// ---------------------------------------------------------------------------
// K3: intra-normalize over D per (b,k), then global L2 normalize per b.
// ---------------------------------------------------------------------------
__global__ void __launch_bounds__(512)
k3_normalize(float* __restrict__ out) {
    const int b   = blockIdx.x;
    const int tid = threadIdx.x;
    const int kq  = (tid & 15) * 4;
    const int ds  = tid >> 4;

    const float* vb = g_vlad + (size_t)b * DD * KK;

    float ss0 = 0.f, ss1 = 0.f, ss2 = 0.f, ss3 = 0.f;
    for (int d = ds; d < DD; d += 32) {
        float4 v = *(const float4*)(vb + (size_t)d * KK + kq);
        ss0 = fmaf(v.x, v.x, ss0);
        ss1 = fmaf(v.y, v.y, ss1);
        ss2 = fmaf(v.z, v.z, ss2);
        ss3 = fmaf(v.w, v.w, ss3);
    }

    __shared__ float red[32][KK];
    __shared__ float invk[KK];
    __shared__ float gpart[KK];
    __shared__ float ginv;

    *(float4*)&red[ds][kq] = make_float4(ss0, ss1, ss2, ss3);
    __syncthreads();
    if (tid < KK) {
        float t = 0.f;
#pragma unroll
        for (int i = 0; i < 32; i++) t += red[i][tid];
        float nrm = fmaxf(sqrtf(t), 1e-12f);
        float iv = 1.f / nrm;
        invk[tid] = iv;
        gpart[tid] = t * iv * iv;
    }
    __syncthreads();
    if (tid == 0) {
        float gsum = 0.f;
        for (int i = 0; i < KK; i++) gsum += gpart[i];
        ginv = 1.f / fmaxf(sqrtf(gsum), 1e-12f);
    }
    __syncthreads();

    const float gi = ginv;
    const float4 ivk = *(const float4*)&invk[kq];
    float* ob = out + (size_t)b * DD * KK;
    for (int d = ds; d < DD; d += 32) {
        float4 v = *(const float4*)(vb + (size_t)d * KK + kq);
        float4 o = make_float4(v.x * ivk.x * gi, v.y * ivk.y * gi,
                               v.z * ivk.z * gi, v.w * ivk.w * gi);
        *(float4*)(ob + (size_t)d * KK + kq) = o;
    }
}

// ---------------------------------------------------------------------------
extern "C" void kernel_launch(void* const* d_in, const int* in_sizes, int n_in,
                              void* d_out, int out_size) {
    const float* x       = (const float*)d_in[0];  // [32,512,1024]
    const float* conv_w  = (const float*)d_in[1];  // [64,512]
    const float* centers = (const float*)d_in[2];  // [512,64]
    float* out = (float*)d_out;                    // [32, 512*64]

    const int smem1 = 200192;
    const int smem2 = 73728;
    cudaFuncSetAttribute(k1_scores, cudaFuncAttributeMaxDynamicSharedMemorySize, smem1);
    cudaFuncSetAttribute(k2_vlad,   cudaFuncAttributeMaxDynamicSharedMemorySize, smem2);

    k1_scores<<<dim3(4, BB), 512, smem1>>>(x, conv_w);
    k2_vlad<<<dim3(8, BB), 256, smem2>>>(centers);
    k3_normalize<<<BB, 512>>>(out);
}

// round 15
// speedup vs baseline: 1.2698x; 1.2698x over previous
#include <cuda_runtime.h>
#include <cuda_fp16.h>

#define BB 32
#define DD 512
#define KK 64
#define NNN 1024

typedef unsigned int u32;

// Scratch (__device__ globals; allocation-free rule)
__device__ __align__(16) __half g_xh[(size_t)BB * DD * NNN];     // 33.5 MB fp16 x
__device__ __align__(16) __half g_assign[(size_t)BB * KK * NNN]; // 4 MB fp16 assign
__device__ __align__(16) float g_asum_part[(size_t)BB * 8 * KK];
__device__ __align__(16) float g_vlad[(size_t)BB * DD * KK];     // 4 MB

// ---------------- helpers ----------------
__device__ __forceinline__ u32 smem_u32(const void* p) {
    u32 a;
    asm("{ .reg .u64 t; cvta.to.shared.u64 t, %1; cvt.u32.u64 %0, t; }" : "=r"(a) : "l"(p));
    return a;
}
__device__ __forceinline__ u32 pack_h2(float a, float b) {
    u32 r;
    asm("cvt.rn.f16x2.f32 %0, %1, %2;" : "=r"(r) : "f"(b), "f"(a));
    return r;
}
__device__ __forceinline__ void mma16816h(float* c, const u32* a, u32 b0, u32 b1) {
    asm volatile(
        "mma.sync.aligned.m16n8k16.row.col.f32.f16.f16.f32 "
        "{%0,%1,%2,%3},{%4,%5,%6,%7},{%8,%9},{%0,%1,%2,%3};"
        : "+f"(c[0]), "+f"(c[1]), "+f"(c[2]), "+f"(c[3])
        : "r"(a[0]), "r"(a[1]), "r"(a[2]), "r"(a[3]), "r"(b0), "r"(b1));
}
__device__ __forceinline__ void ldsm4(u32* r, u32 a) {
    asm volatile("ldmatrix.sync.aligned.m8n8.x4.shared.b16 {%0,%1,%2,%3}, [%4];"
                 : "=r"(r[0]), "=r"(r[1]), "=r"(r[2]), "=r"(r[3]) : "r"(a));
}
__device__ __forceinline__ void ldsm4t(u32* r, u32 a) {
    asm volatile("ldmatrix.sync.aligned.m8n8.x4.trans.shared.b16 {%0,%1,%2,%3}, [%4];"
                 : "=r"(r[0]), "=r"(r[1]), "=r"(r[2]), "=r"(r[3]) : "r"(a));
}
__device__ __forceinline__ void sts128u(u32 a, uint4 v) {
    asm volatile("st.shared.v4.b32 [%0], {%1,%2,%3,%4};"
                 :: "r"(a), "r"(v.x), "r"(v.y), "r"(v.z), "r"(v.w));
}
__device__ __forceinline__ void sts64u(u32 a, u32 v0, u32 v1) {
    asm volatile("st.shared.v2.b32 [%0], {%1,%2};" :: "r"(a), "r"(v0), "r"(v1));
}
__device__ __forceinline__ uint4 lds128u(u32 a) {
    uint4 v;
    asm volatile("ld.shared.v4.b32 {%0,%1,%2,%3}, [%4];"
                 : "=r"(v.x), "=r"(v.y), "=r"(v.z), "=r"(v.w) : "r"(a));
    return v;
}
__device__ __forceinline__ void cpasync16(u32 dst, const void* src) {
    asm volatile("cp.async.cg.shared.global [%0], [%1], 16;" :: "r"(dst), "l"(src));
}
__device__ __forceinline__ void cp_commit() {
    asm volatile("cp.async.commit_group;" ::: "memory");
}
template <int N>
__device__ __forceinline__ void cp_wait() {
    asm volatile("cp.async.wait_group %0;" :: "n"(N) : "memory");
}
// 8 floats -> 1 uint4 of fp16
__device__ __forceinline__ void cvt8h(const float* f, uint4& h) {
    u32* hp = (u32*)&h;
#pragma unroll
    for (int j = 0; j < 4; j++) hp[j] = pack_h2(f[2 * j], f[2 * j + 1]);
}

// ---------------------------------------------------------------------------
// K1 v3b: D[n=128, k=64] = x^T W^T. 256 thr, 2 CTA/SM, grid (8,32).
// x via 3-stage cp.async fp32 ring + conflict-free convert (lane stride 16B).
// W register-prefetched fp16 double buffer. Fused softmax, assign fp16
// (k-major) + asum partials, writes g_xh cache.
// FIXES vs R14: guarded issue() (no phantom chunks / OOB), cp_wait<0> drain
// before the score overlay reuses the ring region.
// Smem: ring 3 x [32 d x 528B] = 50688 | Xh 2 x [32 d x 272B] = 17408 @ 50688
//       W 2 x [64 k x 80B] = 10240 @ 68096. Total 78336.
// ---------------------------------------------------------------------------
__global__ void __launch_bounds__(256, 2)
k1_scores(const float* __restrict__ x, const float* __restrict__ w) {
    extern __shared__ __align__(16) char dyn[];
    float* smf = reinterpret_cast<float*>(dyn);
    const u32 sb = smem_u32(dyn);
    const u32 XH = sb + 50688u;
    const u32 WB = sb + 68096u;

    const int tid = threadIdx.x;
    const int b   = blockIdx.y;
    const int n0  = blockIdx.x * 128;
    const float* xb = x + (size_t)b * DD * NNN;

    const int lane = tid & 31, wid = tid >> 5;
    const int wm = wid >> 1, wn = wid & 1;
    const int g = lane >> 2, tig = lane & 3;
    const int fr = lane & 7, fi = lane >> 3;

    const u32 aoff0 = (u32)((((fi >> 1) * 8) + fr) * 272 + (wm * 32 + (fi & 1) * 8) * 2);
    const u32 boff0 = (u32)((wn * 32 + (fi >> 1) * 8 + fr) * 80 + (fi & 1) * 16);

    const int wk = tid >> 2, wp = (tid & 3) * 8;   // W staging roles

    float c[2][4][4];
#pragma unroll
    for (int i = 0; i < 2; i++)
#pragma unroll
        for (int j = 0; j < 4; j++)
#pragma unroll
            for (int q = 0; q < 4; q++) c[i][j][q] = 0.f;

    // cp.async issue of x chunk ch: 32 d rows x 128 n fp32 = 1024 x 16B
    auto issue = [&](int ch) {
        const u32 ST = sb + (u32)(ch % 3) * 16896u;
        const int dc = ch * 32;
#pragma unroll
        for (int r = 0; r < 4; r++) {
            const int idx = tid + r * 256;
            const int row = idx >> 5, p = idx & 31;
            cpasync16(ST + (u32)(row * 528 + p * 16),
                      xb + (size_t)(dc + row) * NNN + n0 + p * 4);
        }
    };

    // W chunk staging (register prefetch -> fp16 STS)
    float4 wv0, wv1;
    auto ldW = [&](int dc) {
        const float* q = w + (size_t)wk * DD + dc + wp;
        wv0 = *(const float4*)q;
        wv1 = *(const float4*)(q + 4);
    };
    auto stW = [&](int buf) {
        float f[8] = {wv0.x, wv0.y, wv0.z, wv0.w, wv1.x, wv1.y, wv1.z, wv1.w};
        uint4 h;
        cvt8h(f, h);
        sts128u(WB + (u32)buf * 5120u + (u32)(wk * 80 + wp * 2), h);
    };

    // prologue
    issue(0); cp_commit();
    issue(1); cp_commit();
    issue(2); cp_commit();
    ldW(0); stW(0);

    const int NCH = 16;
    for (int ch = 0; ch < NCH; ch++) {
        cp_wait<2>();
        __syncthreads();   // ring[ch%3] visible to all; W[ch&1] visible
        // convert: ring fp32 -> Xh[ch&1] fp16 + g_xh (conflict-free patterns)
        {
            const u32 ST = sb + (u32)(ch % 3) * 16896u;
            const u32 XD = XH + (u32)(ch & 1) * 8704u;
#pragma unroll
            for (int r = 0; r < 4; r++) {
                const int idx = tid + r * 256;
                const int row = idx >> 5, p = idx & 31;
                uint4 v = lds128u(ST + (u32)(row * 528 + p * 16));
                float f0 = __uint_as_float(v.x), f1 = __uint_as_float(v.y);
                float f2 = __uint_as_float(v.z), f3 = __uint_as_float(v.w);
                u32 h0 = pack_h2(f0, f1), h1 = pack_h2(f2, f3);
                sts64u(XD + (u32)(row * 272 + p * 8), h0, h1);
                uint2 hv = make_uint2(h0, h1);
                *reinterpret_cast<uint2*>(
                    g_xh + ((size_t)b * DD + ch * 32 + row) * NNN + n0 + p * 4) = hv;
            }
        }
        if (ch + 1 < NCH) ldW((ch + 1) * 32);
        __syncthreads();   // Xh complete; ring stage free for reuse
        if (ch + 3 < NCH) issue(ch + 3);   // FIX: guarded (no phantom chunks)
        cp_commit();
        // MMA on Xh[ch&1] + W[ch&1]
        const u32 XB = XH + (u32)(ch & 1) * 8704u;
        const u32 WH = WB + (u32)(ch & 1) * 5120u;
#pragma unroll
        for (int ks = 0; ks < 2; ks++) {
            u32 bh[8];
            ldsm4(bh,     WH + boff0 + ks * 32);
            ldsm4(bh + 4, WH + boff0 + ks * 32 + 1280);
            u32 ah[2][4];
#pragma unroll
            for (int mt = 0; mt < 2; mt++)
                ldsm4t(ah[mt], XB + aoff0 + ks * 4352 + mt * 32);
#pragma unroll
            for (int mt = 0; mt < 2; mt++)
#pragma unroll
                for (int nt = 0; nt < 4; nt++)
                    mma16816h(c[mt][nt], ah[mt], bh[2 * nt], bh[2 * nt + 1]);
        }
        if (ch + 1 < NCH) stW((ch + 1) & 1);
    }
    cp_wait<0>();      // FIX: drain all async groups before reusing ring region
    __syncthreads();

    // scores -> smem overlay [128][65] f32 (ring region)
#pragma unroll
    for (int mt = 0; mt < 2; mt++) {
        const int r0 = wm * 32 + mt * 16 + g;
#pragma unroll
        for (int nt = 0; nt < 4; nt++) {
            const int col = wn * 32 + nt * 8 + 2 * tig;
            smf[r0 * 65 + col]           = c[mt][nt][0];
            smf[r0 * 65 + col + 1]       = c[mt][nt][1];
            smf[(r0 + 8) * 65 + col]     = c[mt][nt][2];
            smf[(r0 + 8) * 65 + col + 1] = c[mt][nt][3];
        }
    }
    __syncthreads();

    // softmax over k per n-row
    if (tid < 128) {
        float r[64];
#pragma unroll
        for (int i = 0; i < 64; i++) r[i] = smf[tid * 65 + i];
        float mx = r[0];
#pragma unroll
        for (int i = 1; i < 64; i++) mx = fmaxf(mx, r[i]);
        float s = 0.f;
#pragma unroll
        for (int i = 0; i < 64; i++) { r[i] = __expf(r[i] - mx); s += r[i]; }
        const float is = 1.f / s;
#pragma unroll
        for (int i = 0; i < 64; i++) smf[tid * 65 + i] = r[i] * is;
    }
    __syncthreads();

    if (tid < 64) {   // asum partial for this n-tile
        float s = 0.f;
        for (int rw = 0; rw < 128; rw++) s += smf[rw * 65 + tid];
        g_asum_part[((size_t)b * 8 + blockIdx.x) * KK + tid] = s;
    }
    {   // assign -> fp16 single plane, k-major
        const int k  = tid >> 2;
        const int ns = (tid & 3) * 32;
        __half* oh = g_assign + ((size_t)b * KK + k) * NNN + n0 + ns;
#pragma unroll
        for (int j = 0; j < 32; j += 2) {
            float a0 = smf[(ns + j) * 65 + k];
            float a1 = smf[(ns + j + 1) * 65 + k];
            *reinterpret_cast<u32*>(oh + j) = pack_h2(a0, a1);
        }
    }
}

// ---------------------------------------------------------------------------
// K2: D[d=64, k=64] = x_h · assign^T over n=1024, 4-stage cp.async pipeline,
// n-chunk 64 (16 chunks). Grid (8, 32) = 256 CTAs, 256 thr, 2 CTA/SM.
// Warp tile 32d x 16k (8 warps). Fused "- centers * asum" epilogue.
// Dyn smem: A[4][64 x 144B] = 36864; B[4][64 x 144B] = 36864. Total 73728.
// (unchanged from R12, the proven 51.7us component)
// ---------------------------------------------------------------------------
__global__ void __launch_bounds__(256, 2)
k2_vlad(const float* __restrict__ centers) {
    extern __shared__ __align__(16) char dyn[];
    __shared__ float s_asum[KK];
    const u32 sb = smem_u32(dyn);

    const int tid = threadIdx.x;
    const int b   = blockIdx.y;
    const int d0  = blockIdx.x * 64;

    const int lane = tid & 31, wid = tid >> 5;
    const int wm = wid >> 2, wn = wid & 3;
    const int g = lane >> 2, tig = lane & 3;
    const int fr = lane & 7, fi = lane >> 3;

    const u32 aoff0 = (u32)((wm * 32 + (fi & 1) * 8 + fr) * 144 + ((fi >> 1) * 8) * 2);
    const u32 boff0 = (u32)((wn * 16 + (fi >> 1) * 8 + fr) * 144 + (fi & 1) * 16);

    if (tid < 64) {
        float s = 0.f;
#pragma unroll
        for (int q = 0; q < 8; q++) s += g_asum_part[((size_t)b * 8 + q) * KK + tid];
        s_asum[tid] = s;
    }

    const __half* xhp = g_xh + ((size_t)b * DD + d0) * NNN;
    const __half* ahp = g_assign + (size_t)b * KK * NNN;

    float c[2][2][4];
#pragma unroll
    for (int i = 0; i < 2; i++)
#pragma unroll
        for (int j = 0; j < 2; j++)
#pragma unroll
            for (int q = 0; q < 4; q++) c[i][j][q] = 0.f;

    auto issue = [&](int ch) {
        const int st = ch & 3;
        const int nc = ch * 64;
        const u32 AB = sb + (u32)st * 9216u;
        const u32 BBF = sb + 36864u + (u32)st * 9216u;
#pragma unroll
        for (int r = 0; r < 2; r++) {
            const int cidx = tid + r * 256;
            const int row = cidx >> 3, piece = cidx & 7;
            cpasync16(AB + (u32)(row * 144 + piece * 16),
                      xhp + (size_t)row * NNN + nc + piece * 8);
            cpasync16(BBF + (u32)(row * 144 + piece * 16),
                      ahp + (size_t)row * NNN + nc + piece * 8);
        }
    };

    issue(0); cp_commit();
    issue(1); cp_commit();
    issue(2); cp_commit();

    const int NCH = 16;
    for (int ch = 0; ch < NCH; ch++) {
        cp_wait<2>();
        __syncthreads();
        const u32 AH = sb + (u32)(ch & 3) * 9216u;
        const u32 BH = sb + 36864u + (u32)(ch & 3) * 9216u;
#pragma unroll
        for (int ks = 0; ks < 4; ks++) {
            u32 bh[4];
            ldsm4(bh, BH + boff0 + ks * 32);
            u32 ah[2][4];
#pragma unroll
            for (int mt = 0; mt < 2; mt++)
                ldsm4(ah[mt], AH + aoff0 + ks * 32 + (u32)mt * 2304u);
#pragma unroll
            for (int mt = 0; mt < 2; mt++)
#pragma unroll
                for (int nt = 0; nt < 2; nt++)
                    mma16816h(c[mt][nt], ah[mt], bh[2 * nt], bh[2 * nt + 1]);
        }
        __syncthreads();
        if (ch + 3 < NCH) issue(ch + 3);
        cp_commit();
    }

    // epilogue: vlad[d][k] = D - centers[d][k] * asum[k]
#pragma unroll
    for (int mt = 0; mt < 2; mt++) {
        const int dr0 = d0 + wm * 32 + mt * 16 + g;
        const int dr1 = dr0 + 8;
#pragma unroll
        for (int nt = 0; nt < 2; nt++) {
            const int k = wn * 16 + nt * 8 + 2 * tig;
            const float as0 = s_asum[k], as1 = s_asum[k + 1];
            float2 cv0 = *(const float2*)(centers + (size_t)dr0 * KK + k);
            float2 o0  = make_float2(c[mt][nt][0] - cv0.x * as0,
                                     c[mt][nt][1] - cv0.y * as1);
            *(float2*)(g_vlad + ((size_t)b * DD + dr0) * KK + k) = o0;
            float2 cv1 = *(const float2*)(centers + (size_t)dr1 * KK + k);
            float2 o1  = make_float2(c[mt][nt][2] - cv1.x * as0,
                                     c[mt][nt][3] - cv1.y * as1);
            *(float2*)(g_vlad + ((size_t)b * DD + dr1) * KK + k) = o1;
        }
    }
}

// ---------------------------------------------------------------------------
// K3: intra-normalize over D per (b,k), then global L2 normalize per b.
// (unchanged)
// ---------------------------------------------------------------------------
__global__ void __launch_bounds__(512)
k3_normalize(float* __restrict__ out) {
    const int b   = blockIdx.x;
    const int tid = threadIdx.x;
    const int kq  = (tid & 15) * 4;
    const int ds  = tid >> 4;

    const float* vb = g_vlad + (size_t)b * DD * KK;

    float ss0 = 0.f, ss1 = 0.f, ss2 = 0.f, ss3 = 0.f;
    for (int d = ds; d < DD; d += 32) {
        float4 v = *(const float4*)(vb + (size_t)d * KK + kq);
        ss0 = fmaf(v.x, v.x, ss0);
        ss1 = fmaf(v.y, v.y, ss1);
        ss2 = fmaf(v.z, v.z, ss2);
        ss3 = fmaf(v.w, v.w, ss3);
    }

    __shared__ float red[32][KK];
    __shared__ float invk[KK];
    __shared__ float gpart[KK];
    __shared__ float ginv;

    *(float4*)&red[ds][kq] = make_float4(ss0, ss1, ss2, ss3);
    __syncthreads();
    if (tid < KK) {
        float t = 0.f;
#pragma unroll
        for (int i = 0; i < 32; i++) t += red[i][tid];
        float nrm = fmaxf(sqrtf(t), 1e-12f);
        float iv = 1.f / nrm;
        invk[tid] = iv;
        gpart[tid] = t * iv * iv;
    }
    __syncthreads();
    if (tid == 0) {
        float gsum = 0.f;
        for (int i = 0; i < KK; i++) gsum += gpart[i];
        ginv = 1.f / fmaxf(sqrtf(gsum), 1e-12f);
    }
    __syncthreads();

    const float gi = ginv;
    const float4 ivk = *(const float4*)&invk[kq];
    float* ob = out + (size_t)b * DD * KK;
    for (int d = ds; d < DD; d += 32) {
        float4 v = *(const float4*)(vb + (size_t)d * KK + kq);
        float4 o = make_float4(v.x * ivk.x * gi, v.y * ivk.y * gi,
                               v.z * ivk.z * gi, v.w * ivk.w * gi);
        *(float4*)(ob + (size_t)d * KK + kq) = o;
    }
}

// ---------------------------------------------------------------------------
extern "C" void kernel_launch(void* const* d_in, const int* in_sizes, int n_in,
                              void* d_out, int out_size) {
    const float* x       = (const float*)d_in[0];  // [32,512,1024]
    const float* conv_w  = (const float*)d_in[1];  // [64,512]
    const float* centers = (const float*)d_in[2];  // [512,64]
    float* out = (float*)d_out;                    // [32, 512*64]

    const int smem1 = 78336;
    const int smem2 = 73728;
    cudaFuncSetAttribute(k1_scores, cudaFuncAttributeMaxDynamicSharedMemorySize, smem1);
    cudaFuncSetAttribute(k2_vlad,   cudaFuncAttributeMaxDynamicSharedMemorySize, smem2);

    k1_scores<<<dim3(8, BB), 256, smem1>>>(x, conv_w);
    k2_vlad<<<dim3(8, BB), 256, smem2>>>(centers);
    k3_normalize<<<BB, 512>>>(out);
}

// round 16
// speedup vs baseline: 1.3618x; 1.0725x over previous
#include <cuda_runtime.h>
#include <cuda_fp16.h>

#define BB 32
#define DD 512
#define KK 64
#define NNN 1024

typedef unsigned int u32;

// Scratch (__device__ globals; allocation-free rule)
__device__ __align__(16) __half g_xh[(size_t)BB * DD * NNN];     // 33.5 MB fp16 x
__device__ __align__(16) __half g_assign[(size_t)BB * KK * NNN]; // 4 MB fp16 assign
__device__ __align__(16) float g_asum_part[(size_t)BB * 8 * KK];
__device__ __align__(16) float g_vlad[(size_t)BB * DD * KK];     // 4 MB

// ---------------- helpers ----------------
__device__ __forceinline__ u32 smem_u32(const void* p) {
    u32 a;
    asm("{ .reg .u64 t; cvta.to.shared.u64 t, %1; cvt.u32.u64 %0, t; }" : "=r"(a) : "l"(p));
    return a;
}
__device__ __forceinline__ u32 pack_h2(float a, float b) {
    u32 r;
    asm("cvt.rn.f16x2.f32 %0, %1, %2;" : "=r"(r) : "f"(b), "f"(a));
    return r;
}
__device__ __forceinline__ void mma16816h(float* c, const u32* a, u32 b0, u32 b1) {
    asm volatile(
        "mma.sync.aligned.m16n8k16.row.col.f32.f16.f16.f32 "
        "{%0,%1,%2,%3},{%4,%5,%6,%7},{%8,%9},{%0,%1,%2,%3};"
        : "+f"(c[0]), "+f"(c[1]), "+f"(c[2]), "+f"(c[3])
        : "r"(a[0]), "r"(a[1]), "r"(a[2]), "r"(a[3]), "r"(b0), "r"(b1));
}
__device__ __forceinline__ void ldsm4(u32* r, u32 a) {
    asm volatile("ldmatrix.sync.aligned.m8n8.x4.shared.b16 {%0,%1,%2,%3}, [%4];"
                 : "=r"(r[0]), "=r"(r[1]), "=r"(r[2]), "=r"(r[3]) : "r"(a));
}
__device__ __forceinline__ void ldsm4t(u32* r, u32 a) {
    asm volatile("ldmatrix.sync.aligned.m8n8.x4.trans.shared.b16 {%0,%1,%2,%3}, [%4];"
                 : "=r"(r[0]), "=r"(r[1]), "=r"(r[2]), "=r"(r[3]) : "r"(a));
}
__device__ __forceinline__ void sts128u(u32 a, uint4 v) {
    asm volatile("st.shared.v4.b32 [%0], {%1,%2,%3,%4};"
                 :: "r"(a), "r"(v.x), "r"(v.y), "r"(v.z), "r"(v.w));
}
__device__ __forceinline__ void cpasync16(u32 dst, const void* src) {
    asm volatile("cp.async.cg.shared.global [%0], [%1], 16;" :: "r"(dst), "l"(src));
}
__device__ __forceinline__ void cp_commit() {
    asm volatile("cp.async.commit_group;" ::: "memory");
}
template <int N>
__device__ __forceinline__ void cp_wait() {
    asm volatile("cp.async.wait_group %0;" :: "n"(N) : "memory");
}
// 8 floats -> 1 uint4 of fp16
__device__ __forceinline__ void cvt8h(const float* f, uint4& h) {
    u32* hp = (u32*)&h;
#pragma unroll
    for (int j = 0; j < 4; j++) hp[j] = pack_h2(f[2 * j], f[2 * j + 1]);
}

// ---------------------------------------------------------------------------
// K1 (R12 structure + distance-2 software pipeline): D[n=128, k=64] = x^T W^T,
// fp16 single planes, register-staged LDG. Writes g_xh cache, fused softmax,
// assign fp16 (k-major) + asum partials. Grid (8,32), 256 thr, 2 CTA/SM.
// Dyn smem: X[2buf][32 x 272B] = 17408; W[2buf][64 x 80B] = 10240 @ 17408.
// Score overlay f32[128][65] = 33280.
// ---------------------------------------------------------------------------
__global__ void __launch_bounds__(256, 2)
k1_scores(const float* __restrict__ x, const float* __restrict__ w) {
    extern __shared__ __align__(16) char dyn[];
    float* smf = reinterpret_cast<float*>(dyn);
    const u32 sb = smem_u32(dyn);

    const int tid = threadIdx.x;
    const int b   = blockIdx.y;
    const int n0  = blockIdx.x * 128;
    const float* xb = x + (size_t)b * DD * NNN;

    const int lane = tid & 31, wid = tid >> 5;
    const int wm = wid >> 1, wn = wid & 1;
    const int g = lane >> 2, tig = lane & 3;
    const int fr = lane & 7, fi = lane >> 3;

    const u32 aoff0 = (u32)((((fi >> 1) * 8) + fr) * 272 + (wm * 32 + (fi & 1) * 8) * 2);
    const u32 boff0 = (u32)((wn * 32 + (fi >> 1) * 8 + fr) * 80 + (fi & 1) * 16);

    const int sd = tid >> 3, sc = (tid & 7) * 8;
    const int wk = tid >> 2, wp = (tid & 3) * 8;

    float c[2][4][4];
#pragma unroll
    for (int i = 0; i < 2; i++)
#pragma unroll
        for (int j = 0; j < 4; j++)
#pragma unroll
            for (int q = 0; q < 4; q++) c[i][j][q] = 0.f;

    float4 xv0, xv1, xv2, xv3, wv0, wv1;
    auto ldC = [&](int dc) {
        const float* p = xb + (size_t)(dc + sd) * NNN + n0 + sc;
        xv0 = *(const float4*)p;
        xv1 = *(const float4*)(p + 4);
        xv2 = *(const float4*)(p + 64);
        xv3 = *(const float4*)(p + 68);
        const float* q = w + (size_t)wk * DD + dc + wp;
        wv0 = *(const float4*)q;
        wv1 = *(const float4*)(q + 4);
    };
    auto stC = [&](int buf, int dc) {
        const u32 XB = sb + buf * 8704u;
        __half* xo = g_xh + ((size_t)b * DD + dc + sd) * NNN + n0 + sc;
        {
            float f[8] = {xv0.x, xv0.y, xv0.z, xv0.w, xv1.x, xv1.y, xv1.z, xv1.w};
            uint4 h;
            cvt8h(f, h);
            sts128u(XB + (u32)(sd * 272 + sc * 2), h);
            *reinterpret_cast<uint4*>(xo) = h;
        }
        {
            float f[8] = {xv2.x, xv2.y, xv2.z, xv2.w, xv3.x, xv3.y, xv3.z, xv3.w};
            uint4 h;
            cvt8h(f, h);
            sts128u(XB + (u32)(sd * 272 + sc * 2 + 128), h);
            *reinterpret_cast<uint4*>(xo + 64) = h;
        }
        {
            float f[8] = {wv0.x, wv0.y, wv0.z, wv0.w, wv1.x, wv1.y, wv1.z, wv1.w};
            uint4 h;
            cvt8h(f, h);
            const u32 WH = sb + 17408u + buf * 5120u;
            sts128u(WH + (u32)(wk * 80 + wp * 2), h);
        }
    };

    // prologue: chunk0 staged; chunk1 LDG in flight
    ldC(0);
    stC(0, 0);
    ldC(1 * 32);
    __syncthreads();

    const int NCH = 16;
    for (int ch = 0; ch < NCH; ch++) {
        const int buf = ch & 1;
        // stage chunk ch+1 (regs from ldC issued last iteration)
        if (ch + 1 < NCH) stC(buf ^ 1, (ch + 1) * 32);
        // issue LDG for chunk ch+2 — covered by MMA(ch) + next iteration header
        if (ch + 2 < NCH) ldC((ch + 2) * 32);
        // MMA on buffer staged in the previous iteration
        const u32 XB = sb + buf * 8704u;
        const u32 WH = sb + 17408u + buf * 5120u;
#pragma unroll
        for (int ks = 0; ks < 2; ks++) {
            u32 bh[8];
            ldsm4(bh,     WH + boff0 + ks * 32);
            ldsm4(bh + 4, WH + boff0 + ks * 32 + 1280);
            u32 ah[2][4];
#pragma unroll
            for (int mt = 0; mt < 2; mt++)
                ldsm4t(ah[mt], XB + aoff0 + ks * 4352 + mt * 32);
#pragma unroll
            for (int mt = 0; mt < 2; mt++)
#pragma unroll
                for (int nt = 0; nt < 4; nt++)
                    mma16816h(c[mt][nt], ah[mt], bh[2 * nt], bh[2 * nt + 1]);
        }
        __syncthreads();
    }

    // scores -> smem overlay [128][65] f32
#pragma unroll
    for (int mt = 0; mt < 2; mt++) {
        const int r0 = wm * 32 + mt * 16 + g;
#pragma unroll
        for (int nt = 0; nt < 4; nt++) {
            const int col = wn * 32 + nt * 8 + 2 * tig;
            smf[r0 * 65 + col]           = c[mt][nt][0];
            smf[r0 * 65 + col + 1]       = c[mt][nt][1];
            smf[(r0 + 8) * 65 + col]     = c[mt][nt][2];
            smf[(r0 + 8) * 65 + col + 1] = c[mt][nt][3];
        }
    }
    __syncthreads();

    // softmax over k per n-row
    if (tid < 128) {
        float r[64];
#pragma unroll
        for (int i = 0; i < 64; i++) r[i] = smf[tid * 65 + i];
        float mx = r[0];
#pragma unroll
        for (int i = 1; i < 64; i++) mx = fmaxf(mx, r[i]);
        float s = 0.f;
#pragma unroll
        for (int i = 0; i < 64; i++) { r[i] = __expf(r[i] - mx); s += r[i]; }
        const float is = 1.f / s;
#pragma unroll
        for (int i = 0; i < 64; i++) smf[tid * 65 + i] = r[i] * is;
    }
    __syncthreads();

    if (tid < 64) {  // asum partial for this n-tile
        float s = 0.f;
        for (int rw = 0; rw < 128; rw++) s += smf[rw * 65 + tid];
        g_asum_part[((size_t)b * 8 + blockIdx.x) * KK + tid] = s;
    }
    {   // assign -> fp16 single plane, k-major
        const int k  = tid >> 2;
        const int ns = (tid & 3) * 32;
        __half* oh = g_assign + ((size_t)b * KK + k) * NNN + n0 + ns;
#pragma unroll
        for (int j = 0; j < 32; j += 2) {
            float a0 = smf[(ns + j) * 65 + k];
            float a1 = smf[(ns + j + 1) * 65 + k];
            *reinterpret_cast<u32*>(oh + j) = pack_h2(a0, a1);
        }
    }
}

// ---------------------------------------------------------------------------
// K2: D[d=64, k=64] = x_h · assign^T over n=1024, 5-stage cp.async pipeline
// (issue distance 4, wait<3>), n-chunk 64. Grid (8, 32), 256 thr, 2 CTA/SM.
// Warp tile 32d x 16k. Fused "- centers * asum" epilogue.
// Dyn smem: A[5][64 x 144B] = 46080; B[5][64 x 144B] = 46080. Total 92160.
// ---------------------------------------------------------------------------
__global__ void __launch_bounds__(256, 2)
k2_vlad(const float* __restrict__ centers) {
    extern __shared__ __align__(16) char dyn[];
    __shared__ float s_asum[KK];
    const u32 sb = smem_u32(dyn);

    const int tid = threadIdx.x;
    const int b   = blockIdx.y;
    const int d0  = blockIdx.x * 64;

    const int lane = tid & 31, wid = tid >> 5;
    const int wm = wid >> 2, wn = wid & 3;
    const int g = lane >> 2, tig = lane & 3;
    const int fr = lane & 7, fi = lane >> 3;

    const u32 aoff0 = (u32)((wm * 32 + (fi & 1) * 8 + fr) * 144 + ((fi >> 1) * 8) * 2);
    const u32 boff0 = (u32)((wn * 16 + (fi >> 1) * 8 + fr) * 144 + (fi & 1) * 16);

    if (tid < 64) {
        float s = 0.f;
#pragma unroll
        for (int q = 0; q < 8; q++) s += g_asum_part[((size_t)b * 8 + q) * KK + tid];
        s_asum[tid] = s;
    }

    const __half* xhp = g_xh + ((size_t)b * DD + d0) * NNN;
    const __half* ahp = g_assign + (size_t)b * KK * NNN;

    float c[2][2][4];
#pragma unroll
    for (int i = 0; i < 2; i++)
#pragma unroll
        for (int j = 0; j < 2; j++)
#pragma unroll
            for (int q = 0; q < 4; q++) c[i][j][q] = 0.f;

    auto issue = [&](int ch) {
        const int st = ch % 5;
        const int nc = ch * 64;
        const u32 AB = sb + (u32)st * 9216u;
        const u32 BBF = sb + 46080u + (u32)st * 9216u;
#pragma unroll
        for (int r = 0; r < 2; r++) {
            const int cidx = tid + r * 256;
            const int row = cidx >> 3, piece = cidx & 7;
            cpasync16(AB + (u32)(row * 144 + piece * 16),
                      xhp + (size_t)row * NNN + nc + piece * 8);
            cpasync16(BBF + (u32)(row * 144 + piece * 16),
                      ahp + (size_t)row * NNN + nc + piece * 8);
        }
    };

    issue(0); cp_commit();
    issue(1); cp_commit();
    issue(2); cp_commit();
    issue(3); cp_commit();

    const int NCH = 16;
    for (int ch = 0; ch < NCH; ch++) {
        cp_wait<3>();
        __syncthreads();
        const int st = ch % 5;
        const u32 AH = sb + (u32)st * 9216u;
        const u32 BH = sb + 46080u + (u32)st * 9216u;
#pragma unroll
        for (int ks = 0; ks < 4; ks++) {
            u32 bh[4];
            ldsm4(bh, BH + boff0 + ks * 32);
            u32 ah[2][4];
#pragma unroll
            for (int mt = 0; mt < 2; mt++)
                ldsm4(ah[mt], AH + aoff0 + ks * 32 + (u32)mt * 2304u);
#pragma unroll
            for (int mt = 0; mt < 2; mt++)
#pragma unroll
                for (int nt = 0; nt < 2; nt++)
                    mma16816h(c[mt][nt], ah[mt], bh[2 * nt], bh[2 * nt + 1]);
        }
        __syncthreads();
        if (ch + 4 < NCH) issue(ch + 4);
        cp_commit();   // empty groups in tail keep wait arithmetic uniform
    }

    // epilogue: vlad[d][k] = D - centers[d][k] * asum[k]
#pragma unroll
    for (int mt = 0; mt < 2; mt++) {
        const int dr0 = d0 + wm * 32 + mt * 16 + g;
        const int dr1 = dr0 + 8;
#pragma unroll
        for (int nt = 0; nt < 2; nt++) {
            const int k = wn * 16 + nt * 8 + 2 * tig;
            const float as0 = s_asum[k], as1 = s_asum[k + 1];
            float2 cv0 = *(const float2*)(centers + (size_t)dr0 * KK + k);
            float2 o0  = make_float2(c[mt][nt][0] - cv0.x * as0,
                                     c[mt][nt][1] - cv0.y * as1);
            *(float2*)(g_vlad + ((size_t)b * DD + dr0) * KK + k) = o0;
            float2 cv1 = *(const float2*)(centers + (size_t)dr1 * KK + k);
            float2 o1  = make_float2(c[mt][nt][2] - cv1.x * as0,
                                     c[mt][nt][3] - cv1.y * as1);
            *(float2*)(g_vlad + ((size_t)b * DD + dr1) * KK + k) = o1;
        }
    }
}

// ---------------------------------------------------------------------------
// K3: intra-normalize over D per (b,k), then global L2 normalize per b.
// ---------------------------------------------------------------------------
__global__ void __launch_bounds__(512)
k3_normalize(float* __restrict__ out) {
    const int b   = blockIdx.x;
    const int tid = threadIdx.x;
    const int kq  = (tid & 15) * 4;
    const int ds  = tid >> 4;

    const float* vb = g_vlad + (size_t)b * DD * KK;

    float ss0 = 0.f, ss1 = 0.f, ss2 = 0.f, ss3 = 0.f;
    for (int d = ds; d < DD; d += 32) {
        float4 v = *(const float4*)(vb + (size_t)d * KK + kq);
        ss0 = fmaf(v.x, v.x, ss0);
        ss1 = fmaf(v.y, v.y, ss1);
        ss2 = fmaf(v.z, v.z, ss2);
        ss3 = fmaf(v.w, v.w, ss3);
    }

    __shared__ float red[32][KK];
    __shared__ float invk[KK];
    __shared__ float gpart[KK];
    __shared__ float ginv;

    *(float4*)&red[ds][kq] = make_float4(ss0, ss1, ss2, ss3);
    __syncthreads();
    if (tid < KK) {
        float t = 0.f;
#pragma unroll
        for (int i = 0; i < 32; i++) t += red[i][tid];
        float nrm = fmaxf(sqrtf(t), 1e-12f);
        float iv = 1.f / nrm;
        invk[tid] = iv;
        gpart[tid] = t * iv * iv;
    }
    __syncthreads();
    if (tid == 0) {
        float gsum = 0.f;
        for (int i = 0; i < KK; i++) gsum += gpart[i];
        ginv = 1.f / fmaxf(sqrtf(gsum), 1e-12f);
    }
    __syncthreads();

    const float gi = ginv;
    const float4 ivk = *(const float4*)&invk[kq];
    float* ob = out + (size_t)b * DD * KK;
    for (int d = ds; d < DD; d += 32) {
        float4 v = *(const float4*)(vb + (size_t)d * KK + kq);
        float4 o = make_float4(v.x * ivk.x * gi, v.y * ivk.y * gi,
                               v.z * ivk.z * gi, v.w * ivk.w * gi);
        *(float4*)(ob + (size_t)d * KK + kq) = o;
    }
}

// ---------------------------------------------------------------------------
extern "C" void kernel_launch(void* const* d_in, const int* in_sizes, int n_in,
                              void* d_out, int out_size) {
    const float* x       = (const float*)d_in[0];  // [32,512,1024]
    const float* conv_w  = (const float*)d_in[1];  // [64,512]
    const float* centers = (const float*)d_in[2];  // [512,64]
    float* out = (float*)d_out;                    // [32, 512*64]

    const int smem1 = 33280;
    const int smem2 = 92160;
    cudaFuncSetAttribute(k1_scores, cudaFuncAttributeMaxDynamicSharedMemorySize, smem1);
    cudaFuncSetAttribute(k2_vlad,   cudaFuncAttributeMaxDynamicSharedMemorySize, smem2);

    k1_scores<<<dim3(8, BB), 256, smem1>>>(x, conv_w);
    k2_vlad<<<dim3(8, BB), 256, smem2>>>(centers);
    k3_normalize<<<BB, 512>>>(out);
}

// round 17
// speedup vs baseline: 1.5435x; 1.1334x over previous
#include <cuda_runtime.h>
#include <cuda_fp16.h>

#define BB 32
#define DD 512
#define KK 64
#define NNN 1024

typedef unsigned int u32;

// Scratch (__device__ globals; allocation-free rule)
__device__ __align__(16) __half g_xh[(size_t)BB * DD * NNN];     // 33.5 MB fp16 x
__device__ __align__(16) __half g_assign[(size_t)BB * KK * NNN]; // 4 MB fp16 assign
__device__ __align__(16) float g_asum_part[(size_t)BB * 8 * KK];
__device__ __align__(16) float g_ssq_part[(size_t)BB * 8 * KK];
__device__ __align__(16) float g_vlad[(size_t)BB * DD * KK];     // 4 MB

// ---------------- helpers ----------------
__device__ __forceinline__ u32 smem_u32(const void* p) {
    u32 a;
    asm("{ .reg .u64 t; cvta.to.shared.u64 t, %1; cvt.u32.u64 %0, t; }" : "=r"(a) : "l"(p));
    return a;
}
__device__ __forceinline__ u32 pack_h2(float a, float b) {
    u32 r;
    asm("cvt.rn.f16x2.f32 %0, %1, %2;" : "=r"(r) : "f"(b), "f"(a));
    return r;
}
__device__ __forceinline__ void mma16816h(float* c, const u32* a, u32 b0, u32 b1) {
    asm volatile(
        "mma.sync.aligned.m16n8k16.row.col.f32.f16.f16.f32 "
        "{%0,%1,%2,%3},{%4,%5,%6,%7},{%8,%9},{%0,%1,%2,%3};"
        : "+f"(c[0]), "+f"(c[1]), "+f"(c[2]), "+f"(c[3])
        : "r"(a[0]), "r"(a[1]), "r"(a[2]), "r"(a[3]), "r"(b0), "r"(b1));
}
__device__ __forceinline__ void ldsm4(u32* r, u32 a) {
    asm volatile("ldmatrix.sync.aligned.m8n8.x4.shared.b16 {%0,%1,%2,%3}, [%4];"
                 : "=r"(r[0]), "=r"(r[1]), "=r"(r[2]), "=r"(r[3]) : "r"(a));
}
__device__ __forceinline__ void ldsm4t(u32* r, u32 a) {
    asm volatile("ldmatrix.sync.aligned.m8n8.x4.trans.shared.b16 {%0,%1,%2,%3}, [%4];"
                 : "=r"(r[0]), "=r"(r[1]), "=r"(r[2]), "=r"(r[3]) : "r"(a));
}
__device__ __forceinline__ void sts128u(u32 a, uint4 v) {
    asm volatile("st.shared.v4.b32 [%0], {%1,%2,%3,%4};"
                 :: "r"(a), "r"(v.x), "r"(v.y), "r"(v.z), "r"(v.w));
}
__device__ __forceinline__ void cpasync16(u32 dst, const void* src) {
    asm volatile("cp.async.cg.shared.global [%0], [%1], 16;" :: "r"(dst), "l"(src));
}
__device__ __forceinline__ void cp_commit() {
    asm volatile("cp.async.commit_group;" ::: "memory");
}
template <int N>
__device__ __forceinline__ void cp_wait() {
    asm volatile("cp.async.wait_group %0;" :: "n"(N) : "memory");
}
// 8 floats -> 1 uint4 of fp16
__device__ __forceinline__ void cvt8h(const float* f, uint4& h) {
    u32* hp = (u32*)&h;
#pragma unroll
    for (int j = 0; j < 4; j++) hp[j] = pack_h2(f[2 * j], f[2 * j + 1]);
}

// ---------------------------------------------------------------------------
// K1: D[n=128, k=64] = x^T W^T, fp16 single planes, register-staged LDG,
// distance-2 software pipeline. Writes g_xh cache, fused softmax, assign fp16
// (k-major) + asum partials. Grid (8,32), 256 thr, 2 CTA/SM.
// (unchanged from R16 — 25.3us)
// ---------------------------------------------------------------------------
__global__ void __launch_bounds__(256, 2)
k1_scores(const float* __restrict__ x, const float* __restrict__ w) {
    extern __shared__ __align__(16) char dyn[];
    float* smf = reinterpret_cast<float*>(dyn);
    const u32 sb = smem_u32(dyn);

    const int tid = threadIdx.x;
    const int b   = blockIdx.y;
    const int n0  = blockIdx.x * 128;
    const float* xb = x + (size_t)b * DD * NNN;

    const int lane = tid & 31, wid = tid >> 5;
    const int wm = wid >> 1, wn = wid & 1;
    const int g = lane >> 2, tig = lane & 3;
    const int fr = lane & 7, fi = lane >> 3;

    const u32 aoff0 = (u32)((((fi >> 1) * 8) + fr) * 272 + (wm * 32 + (fi & 1) * 8) * 2);
    const u32 boff0 = (u32)((wn * 32 + (fi >> 1) * 8 + fr) * 80 + (fi & 1) * 16);

    const int sd = tid >> 3, sc = (tid & 7) * 8;
    const int wk = tid >> 2, wp = (tid & 3) * 8;

    float c[2][4][4];
#pragma unroll
    for (int i = 0; i < 2; i++)
#pragma unroll
        for (int j = 0; j < 4; j++)
#pragma unroll
            for (int q = 0; q < 4; q++) c[i][j][q] = 0.f;

    float4 xv0, xv1, xv2, xv3, wv0, wv1;
    auto ldC = [&](int dc) {
        const float* p = xb + (size_t)(dc + sd) * NNN + n0 + sc;
        xv0 = *(const float4*)p;
        xv1 = *(const float4*)(p + 4);
        xv2 = *(const float4*)(p + 64);
        xv3 = *(const float4*)(p + 68);
        const float* q = w + (size_t)wk * DD + dc + wp;
        wv0 = *(const float4*)q;
        wv1 = *(const float4*)(q + 4);
    };
    auto stC = [&](int buf, int dc) {
        const u32 XB = sb + buf * 8704u;
        __half* xo = g_xh + ((size_t)b * DD + dc + sd) * NNN + n0 + sc;
        {
            float f[8] = {xv0.x, xv0.y, xv0.z, xv0.w, xv1.x, xv1.y, xv1.z, xv1.w};
            uint4 h;
            cvt8h(f, h);
            sts128u(XB + (u32)(sd * 272 + sc * 2), h);
            *reinterpret_cast<uint4*>(xo) = h;
        }
        {
            float f[8] = {xv2.x, xv2.y, xv2.z, xv2.w, xv3.x, xv3.y, xv3.z, xv3.w};
            uint4 h;
            cvt8h(f, h);
            sts128u(XB + (u32)(sd * 272 + sc * 2 + 128), h);
            *reinterpret_cast<uint4*>(xo + 64) = h;
        }
        {
            float f[8] = {wv0.x, wv0.y, wv0.z, wv0.w, wv1.x, wv1.y, wv1.z, wv1.w};
            uint4 h;
            cvt8h(f, h);
            const u32 WH = sb + 17408u + buf * 5120u;
            sts128u(WH + (u32)(wk * 80 + wp * 2), h);
        }
    };

    // prologue: chunk0 staged; chunk1 LDG in flight
    ldC(0);
    stC(0, 0);
    ldC(1 * 32);
    __syncthreads();

    const int NCH = 16;
    for (int ch = 0; ch < NCH; ch++) {
        const int buf = ch & 1;
        if (ch + 1 < NCH) stC(buf ^ 1, (ch + 1) * 32);
        if (ch + 2 < NCH) ldC((ch + 2) * 32);
        const u32 XB = sb + buf * 8704u;
        const u32 WH = sb + 17408u + buf * 5120u;
#pragma unroll
        for (int ks = 0; ks < 2; ks++) {
            u32 bh[8];
            ldsm4(bh,     WH + boff0 + ks * 32);
            ldsm4(bh + 4, WH + boff0 + ks * 32 + 1280);
            u32 ah[2][4];
#pragma unroll
            for (int mt = 0; mt < 2; mt++)
                ldsm4t(ah[mt], XB + aoff0 + ks * 4352 + mt * 32);
#pragma unroll
            for (int mt = 0; mt < 2; mt++)
#pragma unroll
                for (int nt = 0; nt < 4; nt++)
                    mma16816h(c[mt][nt], ah[mt], bh[2 * nt], bh[2 * nt + 1]);
        }
        __syncthreads();
    }

    // scores -> smem overlay [128][65] f32
#pragma unroll
    for (int mt = 0; mt < 2; mt++) {
        const int r0 = wm * 32 + mt * 16 + g;
#pragma unroll
        for (int nt = 0; nt < 4; nt++) {
            const int col = wn * 32 + nt * 8 + 2 * tig;
            smf[r0 * 65 + col]           = c[mt][nt][0];
            smf[r0 * 65 + col + 1]       = c[mt][nt][1];
            smf[(r0 + 8) * 65 + col]     = c[mt][nt][2];
            smf[(r0 + 8) * 65 + col + 1] = c[mt][nt][3];
        }
    }
    __syncthreads();

    // softmax over k per n-row
    if (tid < 128) {
        float r[64];
#pragma unroll
        for (int i = 0; i < 64; i++) r[i] = smf[tid * 65 + i];
        float mx = r[0];
#pragma unroll
        for (int i = 1; i < 64; i++) mx = fmaxf(mx, r[i]);
        float s = 0.f;
#pragma unroll
        for (int i = 0; i < 64; i++) { r[i] = __expf(r[i] - mx); s += r[i]; }
        const float is = 1.f / s;
#pragma unroll
        for (int i = 0; i < 64; i++) smf[tid * 65 + i] = r[i] * is;
    }
    __syncthreads();

    if (tid < 64) {  // asum partial for this n-tile
        float s = 0.f;
        for (int rw = 0; rw < 128; rw++) s += smf[rw * 65 + tid];
        g_asum_part[((size_t)b * 8 + blockIdx.x) * KK + tid] = s;
    }
    {   // assign -> fp16 single plane, k-major
        const int k  = tid >> 2;
        const int ns = (tid & 3) * 32;
        __half* oh = g_assign + ((size_t)b * KK + k) * NNN + n0 + ns;
#pragma unroll
        for (int j = 0; j < 32; j += 2) {
            float a0 = smf[(ns + j) * 65 + k];
            float a1 = smf[(ns + j + 1) * 65 + k];
            *reinterpret_cast<u32*>(oh + j) = pack_h2(a0, a1);
        }
    }
}

// ---------------------------------------------------------------------------
// K2: D[d=64, k=64] = x_h · assign^T over n=1024, 5-stage cp.async pipeline,
// n-chunk 64. Grid (8, 32), 256 thr, 2 CTA/SM. Warp tile 32d x 16k.
// Fused "- centers * asum" epilogue, NOW ALSO writes per-tile ssq partials
// (per-k sum of vlad^2 over this CTA's 64 d) for the parallel K3.
// ---------------------------------------------------------------------------
__global__ void __launch_bounds__(256, 2)
k2_vlad(const float* __restrict__ centers) {
    extern __shared__ __align__(16) char dyn[];
    __shared__ float s_asum[KK];
    __shared__ float s_ssq[KK];
    const u32 sb = smem_u32(dyn);

    const int tid = threadIdx.x;
    const int b   = blockIdx.y;
    const int d0  = blockIdx.x * 64;

    const int lane = tid & 31, wid = tid >> 5;
    const int wm = wid >> 2, wn = wid & 3;
    const int g = lane >> 2, tig = lane & 3;
    const int fr = lane & 7, fi = lane >> 3;

    const u32 aoff0 = (u32)((wm * 32 + (fi & 1) * 8 + fr) * 144 + ((fi >> 1) * 8) * 2);
    const u32 boff0 = (u32)((wn * 16 + (fi >> 1) * 8 + fr) * 144 + (fi & 1) * 16);

    if (tid < 64) {
        float s = 0.f;
#pragma unroll
        for (int q = 0; q < 8; q++) s += g_asum_part[((size_t)b * 8 + q) * KK + tid];
        s_asum[tid] = s;
        s_ssq[tid] = 0.f;
    }

    const __half* xhp = g_xh + ((size_t)b * DD + d0) * NNN;
    const __half* ahp = g_assign + (size_t)b * KK * NNN;

    float c[2][2][4];
#pragma unroll
    for (int i = 0; i < 2; i++)
#pragma unroll
        for (int j = 0; j < 2; j++)
#pragma unroll
            for (int q = 0; q < 4; q++) c[i][j][q] = 0.f;

    auto issue = [&](int ch) {
        const int st = ch % 5;
        const int nc = ch * 64;
        const u32 AB = sb + (u32)st * 9216u;
        const u32 BBF = sb + 46080u + (u32)st * 9216u;
#pragma unroll
        for (int r = 0; r < 2; r++) {
            const int cidx = tid + r * 256;
            const int row = cidx >> 3, piece = cidx & 7;
            cpasync16(AB + (u32)(row * 144 + piece * 16),
                      xhp + (size_t)row * NNN + nc + piece * 8);
            cpasync16(BBF + (u32)(row * 144 + piece * 16),
                      ahp + (size_t)row * NNN + nc + piece * 8);
        }
    };

    issue(0); cp_commit();
    issue(1); cp_commit();
    issue(2); cp_commit();
    issue(3); cp_commit();

    const int NCH = 16;
    for (int ch = 0; ch < NCH; ch++) {
        cp_wait<3>();
        __syncthreads();
        const int st = ch % 5;
        const u32 AH = sb + (u32)st * 9216u;
        const u32 BH = sb + 46080u + (u32)st * 9216u;
#pragma unroll
        for (int ks = 0; ks < 4; ks++) {
            u32 bh[4];
            ldsm4(bh, BH + boff0 + ks * 32);
            u32 ah[2][4];
#pragma unroll
            for (int mt = 0; mt < 2; mt++)
                ldsm4(ah[mt], AH + aoff0 + ks * 32 + (u32)mt * 2304u);
#pragma unroll
            for (int mt = 0; mt < 2; mt++)
#pragma unroll
                for (int nt = 0; nt < 2; nt++)
                    mma16816h(c[mt][nt], ah[mt], bh[2 * nt], bh[2 * nt + 1]);
        }
        __syncthreads();
        if (ch + 4 < NCH) issue(ch + 4);
        cp_commit();
    }

    // epilogue: vlad[d][k] = D - centers[d][k]*asum[k]; accumulate ssq per k.
    float ssq[2][2] = {{0.f, 0.f}, {0.f, 0.f}};   // [nt][pair element]
#pragma unroll
    for (int mt = 0; mt < 2; mt++) {
        const int dr0 = d0 + wm * 32 + mt * 16 + g;
        const int dr1 = dr0 + 8;
#pragma unroll
        for (int nt = 0; nt < 2; nt++) {
            const int k = wn * 16 + nt * 8 + 2 * tig;
            const float as0 = s_asum[k], as1 = s_asum[k + 1];
            float2 cv0 = *(const float2*)(centers + (size_t)dr0 * KK + k);
            float2 o0  = make_float2(c[mt][nt][0] - cv0.x * as0,
                                     c[mt][nt][1] - cv0.y * as1);
            *(float2*)(g_vlad + ((size_t)b * DD + dr0) * KK + k) = o0;
            float2 cv1 = *(const float2*)(centers + (size_t)dr1 * KK + k);
            float2 o1  = make_float2(c[mt][nt][2] - cv1.x * as0,
                                     c[mt][nt][3] - cv1.y * as1);
            *(float2*)(g_vlad + ((size_t)b * DD + dr1) * KK + k) = o1;
            ssq[nt][0] = fmaf(o0.x, o0.x, fmaf(o1.x, o1.x, ssq[nt][0]));
            ssq[nt][1] = fmaf(o0.y, o0.y, fmaf(o1.y, o1.y, ssq[nt][1]));
        }
    }
    // reduce over g lanes (lane bits 2..4) via butterfly shuffles
#pragma unroll
    for (int nt = 0; nt < 2; nt++)
#pragma unroll
        for (int j = 0; j < 2; j++) {
#pragma unroll
            for (int m = 4; m <= 16; m <<= 1)
                ssq[nt][j] += __shfl_xor_sync(0xffffffffu, ssq[nt][j], m);
        }
    __syncthreads();   // s_ssq zero-init visible (done in preamble)
    if (g == 0) {      // lanes 0..3 of each warp hold the warp sums
#pragma unroll
        for (int nt = 0; nt < 2; nt++) {
            const int k = wn * 16 + nt * 8 + 2 * tig;
            atomicAdd(&s_ssq[k],     ssq[nt][0]);
            atomicAdd(&s_ssq[k + 1], ssq[nt][1]);
        }
    }
    __syncthreads();
    if (tid < 64)
        g_ssq_part[((size_t)b * 8 + blockIdx.x) * KK + tid] = s_ssq[tid];
}

// ---------------------------------------------------------------------------
// K3 (parallel): grid (8, 32), 256 thr. Each CTA: read ssq partials (2KB),
// compute invk + global ginv redundantly, stream its 64-d slice of vlad once.
// ---------------------------------------------------------------------------
__global__ void __launch_bounds__(256)
k3_normalize(float* __restrict__ out) {
    const int b   = blockIdx.y;
    const int d0  = blockIdx.x * 64;
    const int tid = threadIdx.x;

    __shared__ float invk[KK];
    __shared__ float gpart[KK];
    __shared__ float ginv;

    if (tid < KK) {
        float t = 0.f;
#pragma unroll
        for (int q = 0; q < 8; q++) t += g_ssq_part[((size_t)b * 8 + q) * KK + tid];
        float nrm = fmaxf(sqrtf(t), 1e-12f);
        float iv = 1.f / nrm;
        invk[tid] = iv;
        gpart[tid] = t * iv * iv;
    }
    __syncthreads();
    if (tid == 0) {
        float gsum = 0.f;
        for (int i = 0; i < KK; i++) gsum += gpart[i];
        ginv = 1.f / fmaxf(sqrtf(gsum), 1e-12f);
    }
    __syncthreads();

    const float gi = ginv;
    const int kq = (tid & 15) * 4;   // 4 consecutive k
    const int dr = tid >> 4;         // 16 d rows per pass
    const float4 ivk = *(const float4*)&invk[kq];
    const float* vb = g_vlad + ((size_t)b * DD + d0) * KK;
    float* ob = out + ((size_t)b * DD + d0) * KK;
#pragma unroll
    for (int i = 0; i < 4; i++) {
        const int d = dr + i * 16;
        float4 v = *(const float4*)(vb + (size_t)d * KK + kq);
        float4 o = make_float4(v.x * ivk.x * gi, v.y * ivk.y * gi,
                               v.z * ivk.z * gi, v.w * ivk.w * gi);
        *(float4*)(ob + (size_t)d * KK + kq) = o;
    }
}

// ---------------------------------------------------------------------------
extern "C" void kernel_launch(void* const* d_in, const int* in_sizes, int n_in,
                              void* d_out, int out_size) {
    const float* x       = (const float*)d_in[0];  // [32,512,1024]
    const float* conv_w  = (const float*)d_in[1];  // [64,512]
    const float* centers = (const float*)d_in[2];  // [512,64]
    float* out = (float*)d_out;                    // [32, 512*64]

    const int smem1 = 33280;
    const int smem2 = 92160;
    cudaFuncSetAttribute(k1_scores, cudaFuncAttributeMaxDynamicSharedMemorySize, smem1);
    cudaFuncSetAttribute(k2_vlad,   cudaFuncAttributeMaxDynamicSharedMemorySize, smem2);

    k1_scores<<<dim3(8, BB), 256, smem1>>>(x, conv_w);
    k2_vlad<<<dim3(8, BB), 256, smem2>>>(centers);
    k3_normalize<<<dim3(8, BB), 256>>>(out);
}